// round 5
// baseline (speedup 1.0000x reference)
#include <cuda_runtime.h>
#include <cstdint>

// ---------------- problem constants ----------------
#define N_TOTAL   4096
#define N_IN      1024
#define N_HID     2944
#define N_OUT     128
#define N_MROWS   3072          // matrix rows: nodes 1024..4095
#define BATCH     32
#define T_ITERS   100
#define DT_C      0.05f

// ---------------- kernel config --------------------
#define MAIN_BLOCKS  148
#define MAIN_THREADS 512
#define MAIN_WARPS   (MAIN_THREADS / 32)
#define TOTAL_WARPS  (MAIN_BLOCKS * MAIN_WARPS)

#define MAX_NNZ (4 * 1024 * 1024)   // expected ~812k; huge safety margin

// ---------------- device scratch (no allocs allowed) ----------------
__device__ __align__(16) uint2 g_pairs[MAX_NNZ];   // {col, float bits}
__device__ int       g_row_start[N_MROWS];
__device__ int       g_row_cnt[N_MROWS];
__device__ unsigned  g_nnz_total;

__device__ float g_s0[N_TOTAL * BATCH];            // state ping
__device__ float g_s1[N_TOTAL * BATCH];            // state pong
__device__ float g_noiseT[(size_t)T_ITERS * N_TOTAL * BATCH]; // 52.4 MB, [t][node][b]
__device__ float g_xT[N_IN * BATCH];               // [node][b]
__device__ float g_inv_tau[N_TOTAL];

__device__ unsigned          g_bar_count;          // zero-init; protocol keeps it reset
__device__ volatile unsigned g_bar_gen;

// ---------------- software grid barrier ----------------
__device__ __forceinline__ void grid_barrier() {
    __syncthreads();
    if (threadIdx.x == 0) {
        __threadfence();                                  // publish my writes
        const unsigned gen = g_bar_gen;
        if (atomicAdd(&g_bar_count, 1u) == gridDim.x - 1u) {
            g_bar_count = 0;
            __threadfence();                              // order reset before publish
            g_bar_gen = gen + 1u;
        } else {
            while (g_bar_gen == gen) { }
        }
    }
    __syncthreads();
}

// ---------------- prep: inv_tau + reset nnz counter ----------------
__global__ void prep_kernel(const float* __restrict__ tau) {
    int i = blockIdx.x * blockDim.x + threadIdx.x;
    if (i < N_TOTAL) g_inv_tau[i] = 1.0f / tau[i];
    if (i == 0) g_nnz_total = 0u;
}

// ---------------- build sparse rows from J*mask (warp per row) ----------------
__global__ void build_sparse_kernel(const float* __restrict__ J,
                                    const float* __restrict__ mask) {
    const int warp = (blockIdx.x * blockDim.x + threadIdx.x) >> 5;
    const int lane = threadIdx.x & 31;
    if (warp >= N_MROWS) return;
    const int row = N_IN + warp;
    const float* __restrict__ mrow = mask + (size_t)row * N_TOTAL;
    const float* __restrict__ jrow = J    + (size_t)row * N_TOTAL;

    // pass 1: count (column order = ascending, deterministic)
    int cnt = 0;
    for (int j = lane; j < N_TOTAL; j += 32) {
        unsigned b = __ballot_sync(0xffffffffu, mrow[j] != 0.0f);
        cnt += __popc(b);                         // same value in every lane
    }
    const int cnt_pad = (cnt + 1) & ~1;           // even # pairs -> 16B-aligned chunks
    int base = 0;
    if (lane == 0) base = (int)atomicAdd(&g_nnz_total, (unsigned)cnt_pad);
    base = __shfl_sync(0xffffffffu, base, 0);

    const bool ok = (base + cnt_pad <= MAX_NNZ);
    if (lane == 0) {
        g_row_start[warp] = ok ? base : 0;
        g_row_cnt[warp]   = ok ? cnt  : 0;
    }
    if (!ok) return;

    // pass 2: compact fill (row data is L1-hot from pass 1)
    int pos = base;
    for (int j = lane; j < N_TOTAL; j += 32) {
        const float mv = mrow[j];
        const bool  nz = (mv != 0.0f);
        unsigned b = __ballot_sync(0xffffffffu, nz);
        if (nz) {
            int idx = pos + __popc(b & ((1u << lane) - 1u));
            g_pairs[idx] = make_uint2((unsigned)j, __float_as_uint(jrow[j] * mv));
        }
        pos += __popc(b);
    }
    if (lane == 0 && (cnt & 1)) {                 // padding entry: val=0 -> no effect
        g_pairs[base + cnt] = make_uint2(0u, 0u);
    }
}

// ---------------- transpose noise [t][b][n] -> [t][n][b] ----------------
__global__ void transpose_noise_kernel(const float* __restrict__ noise) {
    __shared__ float tile[32][33];
    const int t  = blockIdx.y;
    const int i0 = blockIdx.x * 32;
    for (int bb = threadIdx.y; bb < 32; bb += 8)
        tile[bb][threadIdx.x] =
            noise[((size_t)t * BATCH + bb) * N_TOTAL + i0 + threadIdx.x];
    __syncthreads();
    for (int ii = threadIdx.y; ii < 32; ii += 8)
        g_noiseT[((size_t)t * N_TOTAL + i0 + ii) * BATCH + threadIdx.x] =
            tile[threadIdx.x][ii];
}

// ---------------- transpose x [b][n] -> [n][b] ----------------
__global__ void transpose_x_kernel(const float* __restrict__ x) {
    __shared__ float tile[32][33];
    const int i0 = blockIdx.x * 32;
    for (int bb = threadIdx.y; bb < 32; bb += 8)
        tile[bb][threadIdx.x] = x[(size_t)bb * N_IN + i0 + threadIdx.x];
    __syncthreads();
    for (int ii = threadIdx.y; ii < 32; ii += 8)
        g_xT[(i0 + ii) * BATCH + threadIdx.x] = tile[threadIdx.x][ii];
}

// ---------------- main persistent recurrence kernel ----------------
// warp = one node per inner step, lane = batch index. s layout [node][batch]:
// every nnz gather is one fully-used 128B line. s reads use __ldcg (L2) because
// the ping-pong buffers are written by other SMs each step (L1 is incoherent).
__global__ void __launch_bounds__(MAIN_THREADS, 1)
soen_main_kernel(const float* __restrict__ gamma,
                 const float* __restrict__ flux,
                 float* __restrict__ out) {
    const int lane  = threadIdx.x & 31;
    const int gwarp = blockIdx.x * MAIN_WARPS + (threadIdx.x >> 5);

    // zero-init s(t=0)
    for (int idx = blockIdx.x * MAIN_THREADS + threadIdx.x;
         idx < N_TOTAL * BATCH; idx += MAIN_BLOCKS * MAIN_THREADS)
        g_s0[idx] = 0.0f;
    grid_barrier();

    for (int t = 0; t < T_ITERS; ++t) {
        const float* __restrict__ src = (t & 1) ? g_s1 : g_s0;
        float*       __restrict__ dst = (t & 1) ? g_s0 : g_s1;
        const float* __restrict__ nz  = g_noiseT + (size_t)t * (N_TOTAL * BATCH);

        for (int i = gwarp; i < N_TOTAL; i += TOTAL_WARPS) {
            // permute node->warp map so heavy output rows spread across SMs
            const int node = (i * 2891) & (N_TOTAL - 1);
            float phi0 = 0.0f, phi1 = 0.0f;

            if (node >= N_IN) {
                const int r    = node - N_IN;
                const int base = g_row_start[r];
                const int cnt2 = (g_row_cnt[r] + 1) & ~1;
                const uint2* __restrict__ pb = g_pairs + base;
                int k = 0;
                // unroll 8 nnz: 8 independent L2 gathers in flight per warp
                for (; k + 8 <= cnt2; k += 8) {
                    const int4 qa = *reinterpret_cast<const int4*>(pb + k);
                    const int4 qb = *reinterpret_cast<const int4*>(pb + k + 2);
                    const int4 qc = *reinterpret_cast<const int4*>(pb + k + 4);
                    const int4 qd = *reinterpret_cast<const int4*>(pb + k + 6);
                    const float sa0 = __ldcg(src + (unsigned)qa.x * BATCH + lane);
                    const float sa1 = __ldcg(src + (unsigned)qa.z * BATCH + lane);
                    const float sb0 = __ldcg(src + (unsigned)qb.x * BATCH + lane);
                    const float sb1 = __ldcg(src + (unsigned)qb.z * BATCH + lane);
                    const float sc0 = __ldcg(src + (unsigned)qc.x * BATCH + lane);
                    const float sc1 = __ldcg(src + (unsigned)qc.z * BATCH + lane);
                    const float sd0 = __ldcg(src + (unsigned)qd.x * BATCH + lane);
                    const float sd1 = __ldcg(src + (unsigned)qd.z * BATCH + lane);
                    phi0 = fmaf(__int_as_float(qa.y), sa0, phi0);
                    phi1 = fmaf(__int_as_float(qa.w), sa1, phi1);
                    phi0 = fmaf(__int_as_float(qb.y), sb0, phi0);
                    phi1 = fmaf(__int_as_float(qb.w), sb1, phi1);
                    phi0 = fmaf(__int_as_float(qc.y), sc0, phi0);
                    phi1 = fmaf(__int_as_float(qc.w), sc1, phi1);
                    phi0 = fmaf(__int_as_float(qd.y), sd0, phi0);
                    phi1 = fmaf(__int_as_float(qd.w), sd1, phi1);
                }
                for (; k < cnt2; k += 2) {
                    const uint2 p0 = pb[k];
                    const uint2 p1 = pb[k + 1];
                    const float s0v = __ldcg(src + (size_t)p0.x * BATCH + lane);
                    const float s1v = __ldcg(src + (size_t)p1.x * BATCH + lane);
                    phi0 = fmaf(__uint_as_float(p0.y), s0v, phi0);
                    phi1 = fmaf(__uint_as_float(p1.y), s1v, phi1);
                }
            }

            float phi = phi0 + phi1 + flux[node];
            if (node < N_IN) phi += g_xT[node * BATCH + lane];
            phi += nz[node * BATCH + lane];
            phi = fminf(fmaxf(phi, -0.5f), 0.5f);

            // make_periodic: ((phi+0.5) mod 1) - 0.5  (phi==+0.5 wraps to -0.5)
            float p = phi + 0.5f;
            p -= floorf(p);
            const float phip = p - 0.5f;

            const float sold = __ldcg(src + node * BATCH + lane);
            const float gact = tanhf(phip) * (1.0f - sold);
            float snew = sold + DT_C * (gamma[node] * gact - sold * g_inv_tau[node]);
            snew = fminf(fmaxf(snew, -1.0f), 1.0f);
            dst[node * BATCH + lane] = snew;

            if (t == T_ITERS - 1 && node >= N_IN + N_HID) {
                out[(size_t)lane * N_OUT + (node - (N_IN + N_HID))] = snew;
            }
        }
        if (t != T_ITERS - 1) grid_barrier();
    }
}

// ---------------- launch ----------------
extern "C" void kernel_launch(void* const* d_in, const int* in_sizes, int n_in,
                              void* d_out, int out_size) {
    const float* x     = (const float*)d_in[0];   // [32, 1024]
    const float* J     = (const float*)d_in[1];   // [4096, 4096]
    const float* gamma = (const float*)d_in[2];   // [4096]
    const float* tau   = (const float*)d_in[3];   // [4096]
    const float* flux  = (const float*)d_in[4];   // [4096]
    const float* mask  = (const float*)d_in[5];   // [4096, 4096]
    const float* noise = (const float*)d_in[6];   // [100, 32, 4096]
    float* out = (float*)d_out;                   // [32, 128]
    (void)in_sizes; (void)n_in; (void)out_size;

    prep_kernel<<<(N_TOTAL + 511) / 512, 512>>>(tau);
    build_sparse_kernel<<<(N_MROWS * 32 + 255) / 256, 256>>>(J, mask);
    transpose_noise_kernel<<<dim3(N_TOTAL / 32, T_ITERS), dim3(32, 8)>>>(noise);
    transpose_x_kernel<<<N_IN / 32, dim3(32, 8)>>>(x);
    soen_main_kernel<<<MAIN_BLOCKS, MAIN_THREADS>>>(gamma, flux, out);
}

// round 6
// speedup vs baseline: 1.5802x; 1.5802x over previous
#include <cuda_runtime.h>
#include <cstdint>

// ---------------- problem constants ----------------
#define N_TOTAL   4096
#define N_IN      1024
#define N_HID     2944
#define N_OUT     128
#define N_MROWS   3072          // matrix rows: nodes 1024..4095
#define BATCH     32
#define T_ITERS   100
#define DT_C      0.05f

// ---------------- kernel config --------------------
#define MAIN_BLOCKS   148
#define MAIN_THREADS  512
#define MAIN_WARPS    (MAIN_THREADS / 32)
#define TOTAL_WARPS   (MAIN_BLOCKS * MAIN_WARPS)   // 2368

#define MAX_NNZ   (4 * 1024 * 1024)
#define SMEM_CAP  1024                              // pairs per warp staged in smem
#define SMEM_BYTES (MAIN_WARPS * SMEM_CAP * 8)      // 128 KB dynamic smem

// pair word0 layout: [30:19]=row (12b), [18:7]=col*128 byte offset (col<<7)
#define OFF_MASK  0x0007FF80u

// ---------------- device scratch (no allocs allowed) ----------------
__device__ __align__(16) uint2 g_pairs[MAX_NNZ];    // {row<<19|col<<7, f32 bits}
__device__ int       g_row_start[N_MROWS + 1];      // padded prefix (deterministic)
__device__ int       g_row_cnt[N_MROWS];            // padded (even) counts
__device__ int       g_W;                           // pairs per warp chunk (even)

__device__ float g_part[N_MROWS * 4 * BATCH];       // per-(row,slot) partial phis
__device__ float g_s0[N_TOTAL * BATCH];             // state ping  [node][batch]
__device__ float g_s1[N_TOTAL * BATCH];             // state pong
__device__ float g_noiseT[(size_t)T_ITERS * N_TOTAL * BATCH]; // [t][node][b]
__device__ float g_xT[N_IN * BATCH];                // [node][b]
__device__ float g_inv_tau[N_TOTAL];

__device__ unsigned          g_bar_count;
__device__ volatile unsigned g_bar_gen;

// ---------------- software grid barrier ----------------
// thread0's __threadfence (gpu scope) emits CCTL.IVALL -> whole-SM L1D
// invalidate at arrival. Nothing is read between IVALL and release, so all
// post-barrier plain loads refill from (fenced) L2. This makes plain
// L1-cached loads of cross-SM data safe within the persistent kernel.
__device__ __forceinline__ void grid_barrier() {
    __syncthreads();
    if (threadIdx.x == 0) {
        __threadfence();
        const unsigned gen = g_bar_gen;
        if (atomicAdd(&g_bar_count, 1u) == gridDim.x - 1u) {
            g_bar_count = 0;
            __threadfence();
            g_bar_gen = gen + 1u;
        } else {
            while (g_bar_gen == gen) { }
        }
    }
    __syncthreads();
}

// ---------------- L0: per-row padded counts + inv_tau ----------------
__global__ void count_kernel(const float* __restrict__ mask,
                             const float* __restrict__ tau) {
    const int gtid = blockIdx.x * blockDim.x + threadIdx.x;
    if (gtid < N_TOTAL) g_inv_tau[gtid] = 1.0f / tau[gtid];

    const int warp = gtid >> 5;
    const int lane = gtid & 31;
    if (warp >= N_MROWS) return;
    const float* __restrict__ mrow = mask + (size_t)(N_IN + warp) * N_TOTAL;

    int cnt = 0;
    for (int j = lane; j < N_TOTAL; j += 32) {
        unsigned b = __ballot_sync(0xffffffffu, mrow[j] != 0.0f);
        cnt += __popc(b);
    }
    if (lane == 0) g_row_cnt[warp] = (cnt + 1) & ~1;   // pad to even
}

// ---------------- L1: exclusive prefix over 3072 padded counts ----------------
__global__ void scan_kernel() {
    __shared__ int sh[32];
    const int t = threadIdx.x;      // 1024 threads
    int off = 0;
    for (int seg = 0; seg < 3; ++seg) {
        int v = g_row_cnt[seg * 1024 + t];
        int x = v;
        #pragma unroll
        for (int d = 1; d < 32; d <<= 1) {
            int y = __shfl_up_sync(0xffffffffu, x, d);
            if ((t & 31) >= d) x += y;
        }
        if ((t & 31) == 31) sh[t >> 5] = x;
        __syncthreads();
        if (t < 32) {
            int x2 = sh[t];
            #pragma unroll
            for (int d = 1; d < 32; d <<= 1) {
                int y = __shfl_up_sync(0xffffffffu, x2, d);
                if (t >= d) x2 += y;
            }
            sh[t] = x2;
        }
        __syncthreads();
        const int incl = x + ((t >= 32) ? sh[(t >> 5) - 1] : 0);
        g_row_start[seg * 1024 + t] = off + incl - v;
        const int segtotal = sh[31];
        __syncthreads();
        off += segtotal;
    }
    if (t == 0) {
        g_row_start[N_MROWS] = off;
        int w = (off + TOTAL_WARPS - 1) / TOTAL_WARPS;
        w = (w + 1) & ~1;
        if (w < 2) w = 2;
        g_W = w;
    }
}

// ---------------- L2: fill flat pair array (deterministic layout) ----------------
__global__ void fill_kernel(const float* __restrict__ J,
                            const float* __restrict__ mask) {
    const int warp = (blockIdx.x * blockDim.x + threadIdx.x) >> 5;
    const int lane = threadIdx.x & 31;
    if (warp >= N_MROWS) return;
    const int row = N_IN + warp;
    const float* __restrict__ mrow = mask + (size_t)row * N_TOTAL;
    const float* __restrict__ jrow = J    + (size_t)row * N_TOTAL;
    const int base = g_row_start[warp];
    const unsigned rtag = (unsigned)warp << 19;

    int pos = base;
    for (int j = lane; j < N_TOTAL; j += 32) {
        const float mv = mrow[j];
        const bool  nz = (mv != 0.0f);
        unsigned b = __ballot_sync(0xffffffffu, nz);
        if (nz) {
            int idx = pos + __popc(b & ((1u << lane) - 1u));
            g_pairs[idx] = make_uint2(rtag | ((unsigned)j << 7),
                                      __float_as_uint(jrow[j] * mv));
        }
        pos += __popc(b);
    }
    const int cnt = pos - base;
    if (lane == 0 && (cnt & 1)) g_pairs[base + cnt] = make_uint2(rtag, 0u); // pad, val=0
}

// ---------------- L3: transpose noise [t][b][n] -> [t][n][b] ----------------
__global__ void transpose_noise_kernel(const float* __restrict__ noise) {
    __shared__ float tile[32][33];
    const int t  = blockIdx.y;
    const int i0 = blockIdx.x * 32;
    for (int bb = threadIdx.y; bb < 32; bb += 8)
        tile[bb][threadIdx.x] =
            noise[((size_t)t * BATCH + bb) * N_TOTAL + i0 + threadIdx.x];
    __syncthreads();
    for (int ii = threadIdx.y; ii < 32; ii += 8)
        g_noiseT[((size_t)t * N_TOTAL + i0 + ii) * BATCH + threadIdx.x] =
            tile[threadIdx.x][ii];
}

// ---------------- L4: transpose x [b][n] -> [n][b] ----------------
__global__ void transpose_x_kernel(const float* __restrict__ x) {
    __shared__ float tile[32][33];
    const int i0 = blockIdx.x * 32;
    for (int bb = threadIdx.y; bb < 32; bb += 8)
        tile[bb][threadIdx.x] = x[(size_t)bb * N_IN + i0 + threadIdx.x];
    __syncthreads();
    for (int ii = threadIdx.y; ii < 32; ii += 8)
        g_xT[(i0 + ii) * BATCH + threadIdx.x] = tile[threadIdx.x][ii];
}

// ---------------- L5: main persistent recurrence kernel ----------------
// Two phases per iteration:
//   phase1: warp w processes flat pairs [w*W,(w+1)*W) (smem-staged), writing
//           per-(row,slot) partial phi vectors. Perfect nnz balance.
//   phase2: warp per node combines <=4 partials in fixed order, applies the
//           activation + state update.
__global__ void __launch_bounds__(MAIN_THREADS, 1)
soen_main_kernel(const float* __restrict__ gamma,
                 const float* __restrict__ flux,
                 float* __restrict__ out) {
    extern __shared__ uint2 sh_pairs[];
    const int lane  = threadIdx.x & 31;
    const int wcta  = threadIdx.x >> 5;
    const int gwarp = blockIdx.x * MAIN_WARPS + wcta;

    const int W     = g_W;
    const int total = g_row_start[N_MROWS];
    const int cbase = gwarp * W;
    int n = total - cbase;
    if (n > W) n = W;
    if (n < 0) n = 0;

    // stage this warp's chunk into smem (once; static schedule)
    const uint2* __restrict__ pbase;
    if (W <= SMEM_CAP) {
        uint2* mych = sh_pairs + wcta * SMEM_CAP;
        for (int j = lane; j < n; j += 32) mych[j] = g_pairs[cbase + j];
        __syncwarp();
        pbase = mych;
    } else {
        pbase = g_pairs + cbase;       // fallback (never expected here)
    }

    // zero-init s(t=0)
    for (int idx = blockIdx.x * MAIN_THREADS + threadIdx.x;
         idx < N_TOTAL * BATCH; idx += MAIN_BLOCKS * MAIN_THREADS)
        g_s0[idx] = 0.0f;
    grid_barrier();

    for (int t = 0; t < T_ITERS; ++t) {
        const float* src = (t & 1) ? g_s1 : g_s0;
        float*       dst = (t & 1) ? g_s0 : g_s1;
        const char*  srcb = (const char*)src + lane * 4;   // + packed byte offset

        // ---------- phase 1: balanced gather of partial phis ----------
        int pos = 0;
        while (pos < n) {
            const unsigned h0 = pbase[pos].x;
            const int row = (int)(h0 >> 19);
            const int rs  = g_row_start[row];
            const int reg = g_row_start[row + 1];
            int run_end = reg - cbase;
            if (run_end > n) run_end = n;
            const int slot = gwarp - rs / W;

            float a0 = 0.0f, a1 = 0.0f, a2 = 0.0f, a3 = 0.0f;
            int k = pos;
            for (; k + 16 <= run_end; k += 16) {
                #pragma unroll
                for (int u = 0; u < 8; ++u) {
                    const uint4 q = *reinterpret_cast<const uint4*>(pbase + k + 2 * u);
                    const float sv0 = *reinterpret_cast<const float*>(srcb + (q.x & OFF_MASK));
                    const float sv1 = *reinterpret_cast<const float*>(srcb + (q.z & OFF_MASK));
                    if (u & 1) {
                        a2 = fmaf(__uint_as_float(q.y), sv0, a2);
                        a3 = fmaf(__uint_as_float(q.w), sv1, a3);
                    } else {
                        a0 = fmaf(__uint_as_float(q.y), sv0, a0);
                        a1 = fmaf(__uint_as_float(q.w), sv1, a1);
                    }
                }
            }
            for (; k < run_end; k += 2) {     // runs are even-length
                const uint4 q = *reinterpret_cast<const uint4*>(pbase + k);
                const float sv0 = *reinterpret_cast<const float*>(srcb + (q.x & OFF_MASK));
                const float sv1 = *reinterpret_cast<const float*>(srcb + (q.z & OFF_MASK));
                a0 = fmaf(__uint_as_float(q.y), sv0, a0);
                a1 = fmaf(__uint_as_float(q.w), sv1, a1);
            }
            if (slot >= 0 && slot < 4)
                g_part[((row << 2) + slot) * BATCH + lane] = (a0 + a1) + (a2 + a3);
            pos = run_end;
        }
        grid_barrier();

        // ---------- phase 2: combine + activation + state update ----------
        const float* __restrict__ nzT = g_noiseT + (size_t)t * (N_TOTAL * BATCH);
        for (int node = gwarp; node < N_TOTAL; node += TOTAL_WARPS) {
            const int nb = node * BATCH + lane;
            float phi = 0.0f;
            if (node >= N_IN) {
                const int r  = node - N_IN;
                const int rs = g_row_start[r];
                const int re = g_row_start[r + 1];
                if (re > rs) {
                    const int w0 = rs / W;
                    const int w1 = (re - 1) / W;
                    const int ns = w1 - w0;            // 0..3
                    const float* pp = g_part + (r << 2) * BATCH + lane;
                    phi = pp[0];
                    if (ns >= 1) phi += pp[BATCH];
                    if (ns >= 2) phi += pp[2 * BATCH];
                    if (ns >= 3) phi += pp[3 * BATCH];
                }
            }
            phi += flux[node];
            if (node < N_IN) phi += g_xT[nb];
            phi += nzT[nb];
            phi = fminf(fmaxf(phi, -0.5f), 0.5f);
            const float phip = (phi >= 0.5f) ? -0.5f : phi;  // periodic wrap

            const float sold = src[nb];
            const float gact = tanhf(phip) * (1.0f - sold);
            float snew = sold + DT_C * (gamma[node] * gact - sold * g_inv_tau[node]);
            snew = fminf(fmaxf(snew, -1.0f), 1.0f);
            dst[nb] = snew;

            if (t == T_ITERS - 1 && node >= N_IN + N_HID)
                out[(size_t)lane * N_OUT + (node - (N_IN + N_HID))] = snew;
        }
        if (t != T_ITERS - 1) grid_barrier();
    }
}

// ---------------- launch: exactly 6 launches so ncu -s 5 hits main ----------------
extern "C" void kernel_launch(void* const* d_in, const int* in_sizes, int n_in,
                              void* d_out, int out_size) {
    const float* x     = (const float*)d_in[0];   // [32, 1024]
    const float* J     = (const float*)d_in[1];   // [4096, 4096]
    const float* gamma = (const float*)d_in[2];   // [4096]
    const float* tau   = (const float*)d_in[3];   // [4096]
    const float* flux  = (const float*)d_in[4];   // [4096]
    const float* mask  = (const float*)d_in[5];   // [4096, 4096]
    const float* noise = (const float*)d_in[6];   // [100, 32, 4096]
    float* out = (float*)d_out;                   // [32, 128]
    (void)in_sizes; (void)n_in; (void)out_size;

    cudaFuncSetAttribute(soen_main_kernel,
                         cudaFuncAttributeMaxDynamicSharedMemorySize, SMEM_BYTES);

    count_kernel<<<(N_MROWS * 32 + 511) / 512, 512>>>(mask, tau);          // L0
    scan_kernel<<<1, 1024>>>();                                            // L1
    fill_kernel<<<(N_MROWS * 32 + 255) / 256, 256>>>(J, mask);             // L2
    transpose_noise_kernel<<<dim3(N_TOTAL / 32, T_ITERS), dim3(32, 8)>>>(noise); // L3
    transpose_x_kernel<<<N_IN / 32, dim3(32, 8)>>>(x);                     // L4
    soen_main_kernel<<<MAIN_BLOCKS, MAIN_THREADS, SMEM_BYTES>>>(gamma, flux, out); // L5
}